// round 14
// baseline (speedup 1.0000x reference)
#include <cuda_runtime.h>
#include <math.h>

#define HIDDEN 1024
#define NINTER 256
#define WINDOW 64
#define PAD    8

#define CNT_SHIFT 55
#define FIX_BITS  46
#define FIX_SCALE 70368744177664.0f          // 2^46
#define FIX_BIAS  (1LL << FIX_BITS)          // per-term bias (keeps adds positive)
#define LOW_MASK  ((1ULL << CNT_SHIFT) - 1ULL)

// persistent state (allocation-free rule: __device__ globals).
// g_acc is reset by the publisher each replay (safe: it is the 256th adder,
// and the next replay cannot start until this kernel retires).
// g_est/g_exact carry a 15-bit wrapping epoch in bits [49,64).
__device__ unsigned long long g_acc;       // {count>=55 | biased fixed-point sum}
__device__ unsigned long long g_est;       // {epoch15<<49 | est_lo17<<32}
__device__ unsigned long long g_exact;     // {epoch15<<49 | k17<<32 | et_bits32}

// fp64 exp, rel err ~1e-13 (range reduction + degree-9, Estrin form)
__device__ __forceinline__ double fast_exp(double x) {
    const double LOG2E  = 1.4426950408889634074;
    const double LN2_HI = 6.9314718055994528623e-1;
    const double LN2_LO = 2.3190468138462995584e-17;
    double n = rint(x * LOG2E);
    double r = fma(-n, LN2_HI, x);
    r = fma(-n, LN2_LO, r);
    double p01 = 1.0 + r;
    double p23 = fma(r, 1.6666666666666665741e-1, 5.0e-1);
    double p45 = fma(r, 8.3333333333333332177e-3, 4.1666666666666664354e-2);
    double p67 = fma(r, 1.9841269841269841253e-4, 1.3888888888888889419e-3);
    double p89 = fma(r, 2.7557319223985890653e-6, 2.4801587301587301566e-5);
    double r2 = r * r;
    double q0 = fma(r2, p23, p01);
    double q1 = fma(r2, p67, p45);
    double r4 = r2 * r2;
    double s0 = fma(r4, q1, q0);
    double r8 = r4 * r4;
    double res = fma(r8, p89, s0);
    long long ni = (long long)n;
    double sc = __longlong_as_double((ni + 1023LL) << 52);  // exact 2^n
    return res * sc;
}

// 1/d via fp32 rcp seed + 1 fp64 Newton step (rel err ~2^-44)
__device__ __forceinline__ double fast_recip(double d) {
    double y = (double)__frcp_rn((float)d);
    return y * fma(-d, y, 2.0);
}

// ---------------------------------------------------------------------------
// ONE kernel, grid = 256 x 256. No separate head block.
// Each block (row = bid): MLP term -> atomicAdd-with-return into g_acc
// (count in bits >=55, exact biased fixed-point sum below). The block whose
// return shows count==255 is the PUBLISHER: it already holds the full sum ->
// publishes the fp32 ESTIMATE immediately, issues its own window loads, then
// computes and publishes the EXACT fp64 head under them, then resets g_acc.
// All threads direct-poll the packed epoch words (broadcast L2 reads).
// Deadlock-free: exactly one publisher per replay (g_acc starts at 0);
// every block's epoch read precedes its add (threadfence), so the publisher
// (the 256th add) cannot publish before any block captured the old epoch.
// ---------------------------------------------------------------------------
__global__ void __launch_bounds__(256) fused_attn_kernel(
        const float* __restrict__ hs,
        const float* __restrict__ ht,
        const float* __restrict__ fc1_w,
        const float* __restrict__ fc1_b,
        const float* __restrict__ fc2_w,
        const float* __restrict__ fc2_b,
        float* __restrict__ out, int S) {
    const int tid  = threadIdx.x;
    const int lane = tid & 31;
    const int wid  = tid >> 5;
    const int row  = blockIdx.x;

    __shared__ float    sred[8];
    __shared__ unsigned sh_oldep;
    __shared__ float    colsum[8][36];

    // early scalar prefetch (lands under the vector loads below)
    float bf = 0.f, fw = 0.f, fb2 = 0.f;
    if (tid == 0) {
        bf  = __ldg(&fc1_b[row]);
        fw  = __ldg(&fc2_w[row]);
        fb2 = __ldg(&fc2_b[0]);
    }

    // ------------------- stage A: MLP row -------------------
    float4 w = ((const float4*)(fc1_w + (size_t)row * HIDDEN))[tid];
    float4 h = ((const float4*)ht)[tid];
    double e0 = fma((double)w.y, (double)h.y, (double)w.x * h.x);
    double e1 = fma((double)w.w, (double)h.w, (double)w.z * h.z);
    float accf = (float)(e0 + e1);
    #pragma unroll
    for (int o = 16; o > 0; o >>= 1)
        accf += __shfl_down_sync(0xffffffffu, accf, o);
    if (lane == 0) sred[wid] = accf;
    __syncthreads();                                   // S1

    bool   is_pub = false;
    double z_pub  = 0.0;
    if (tid == 0) {
        // capture old epoch BEFORE our add (fence-ordered): race-free
        unsigned long long west = *(volatile unsigned long long*)&g_est;
        unsigned old_ep = (unsigned)((west >> 49) & 0x7FFFULL);
        sh_oldep = old_ep;
        __threadfence();

        float zf = ((sred[0] + sred[1]) + (sred[2] + sred[3]))
                 + ((sred[4] + sred[5]) + (sred[6] + sred[7]))
                 + bf;
        float term = tanhf(zf) * fw;
        long long fx = __float2ll_rn(term * FIX_SCALE);       // exact
        unsigned long long mine = (1ULL << CNT_SHIFT)
                                + (unsigned long long)(fx + FIX_BIAS);
        unsigned long long oldv = atomicAdd(&g_acc, mine);

        if ((oldv >> CNT_SHIFT) == (unsigned long long)(NINTER - 1)) {
            // PUBLISHER: full exact sum is in hand
            is_pub = true;
            long long lows = (long long)((oldv + mine) & LOW_MASK);
            long long sum_fx = lows - ((long long)NINTER << FIX_BITS);
            z_pub = (double)sum_fx * (1.0 / (double)(1LL << FIX_BITS))
                  + (double)fb2;
            // fast fp32 estimate -> publish immediately
            float zf2 = (float)z_pub;
            float ptf = (float)S * __frcp_rn(1.0f + __expf(-zf2));
            int est_lo = (int)ptf - ((WINDOW - 1) + PAD);
            if (est_lo < 0) est_lo = 0;
            unsigned epoch = (old_ep + 1u) & 0x7FFFu;
            *(volatile unsigned long long*)&g_est =
                ((unsigned long long)epoch << 49)
              | ((unsigned long long)(unsigned)est_lo << 32);
        }
    }
    __syncthreads();                                   // S2

    const unsigned tgt = (sh_oldep + 1u) & 0x7FFFu;

    // direct-poll the ESTIMATE (broadcast L2 read, all threads wake together)
    unsigned long long west;
    do {
        west = *(volatile unsigned long long*)&g_est;
    } while ((unsigned)((west >> 49) & 0x7FFFULL) != tgt);
    const int est_lo = (int)((west >> 32) & 0x1FFFFULL);

    // speculative padded window loads (PAD=8 covers fp32-estimate error)
    const int col    = (row << 2) + (tid & 3);
    const int rowoff = tid >> 2;                       // 0..63
    const float* base = hs + col;
    const int r0 = est_lo + rowoff;
    const int r1 = r0 + 64;
    const int r2 = r0 + 128;

    float v0 = 0.f, v1 = 0.f, v2 = 0.f;
    if (r0 < S) v0 = base[(size_t)r0 * HIDDEN];
    if (r1 < S) v1 = base[(size_t)r1 * HIDDEN];
    if (r2 < S) v2 = base[(size_t)r2 * HIDDEN];

    // PUBLISHER computes the exact head NOW — its loads are already in
    // flight, the fp64 chain runs under them on a different pipe.
    if (is_pub) {
        double e  = fast_exp(-z_pub);
        double pt = (double)S * fast_recip(1.0 + e);
        int k = (int)pt;                               // pt in (0,S), non-int
        float et = __expf((float)(((double)S - pt) * (1.0 / 2048.0)));
        *(volatile unsigned long long*)&g_exact =
            ((unsigned long long)tgt << 49)
          | ((unsigned long long)(unsigned)k << 32)
          | (unsigned long long)(unsigned)__float_as_int(et);
        *(volatile unsigned long long*)&g_acc = 0ULL;  // reset for next replay
    }

    // direct-poll the EXACT head (lands under the loads for non-publishers)
    unsigned long long wex;
    do {
        wex = *(volatile unsigned long long*)&g_exact;
    } while ((unsigned)((wex >> 49) & 0x7FFFULL) != tgt);
    const int   k  = (int)((wex >> 32) & 0x1FFFFULL);
    const float et = __int_as_float((int)(unsigned)wex);

    int ws = k - (WINDOW - 1);  if (ws < 0)     ws = 0;
    int we = k + WINDOW;        if (we > S - 1) we = S - 1;

    float acc = 0.f;
    if (r0 >= ws && r0 <= we) acc += v0;
    if (r1 >= ws && r1 <= we) acc += v1;
    if (r2 >= ws && r2 <= we) acc += v2;

    // fold the 8 rowgroups within each warp (keeps the 4 column lanes)
    #pragma unroll
    for (int o = 16; o >= 4; o >>= 1)
        acc += __shfl_xor_sync(0xffffffffu, acc, o);

    if (lane < 4) colsum[wid][lane] = acc;             // 8 warps x 4 cols
    __syncthreads();                                   // S3

    if (tid < 4) {
        float s = ((colsum[0][tid] + colsum[1][tid])
                 + (colsum[2][tid] + colsum[3][tid]))
                + ((colsum[4][tid] + colsum[5][tid])
                 + (colsum[6][tid] + colsum[7][tid]));
        out[col] = et * s;
    }
}

extern "C" void kernel_launch(void* const* d_in, const int* in_sizes, int n_in,
                              void* d_out, int out_size) {
    const float* hs    = (const float*)d_in[0];
    const float* ht    = (const float*)d_in[1];
    const float* fc1_w = (const float*)d_in[2];
    const float* fc1_b = (const float*)d_in[3];
    const float* fc2_w = (const float*)d_in[4];
    const float* fc2_b = (const float*)d_in[5];

    const int S = in_sizes[0] / HIDDEN;   // host-side constant, capture-safe

    fused_attn_kernel<<<NINTER, 256>>>(hs, ht, fc1_w, fc1_b, fc2_w, fc2_b,
                                       (float*)d_out, S);
}

// round 15
// speedup vs baseline: 1.2216x; 1.2216x over previous
#include <cuda_runtime.h>
#include <math.h>

#define HIDDEN 1024
#define NINTER 256
#define WINDOW 64
#define PAD    8

#define CNT_SHIFT 55
#define FIX_BITS  46
#define FIX_SCALE 70368744177664.0f          // 2^46
#define FIX_BIAS  (1LL << FIX_BITS)          // per-term bias (keeps adds positive)
#define LOW_MASK  ((1ULL << CNT_SHIFT) - 1ULL)

// persistent state (allocation-free rule: __device__ globals).
// g_acc is reset by the publisher each replay (it is the 256th adder; the
// next replay cannot start until this kernel retires).
// g_est/g_exact carry a 15-bit wrapping epoch in bits [49,64).
__device__ unsigned long long g_acc;       // {count>=55 | biased fixed-point sum}
__device__ unsigned long long g_est;       // {epoch15<<49 | est_lo17<<32}
__device__ unsigned long long g_exact;     // {epoch15<<49 | k17<<32 | et_bits32}

// fp64 exp, rel err ~1e-13 (range reduction + degree-9, Estrin form)
__device__ __forceinline__ double fast_exp(double x) {
    const double LOG2E  = 1.4426950408889634074;
    const double LN2_HI = 6.9314718055994528623e-1;
    const double LN2_LO = 2.3190468138462995584e-17;
    double n = rint(x * LOG2E);
    double r = fma(-n, LN2_HI, x);
    r = fma(-n, LN2_LO, r);
    double p01 = 1.0 + r;
    double p23 = fma(r, 1.6666666666666665741e-1, 5.0e-1);
    double p45 = fma(r, 8.3333333333333332177e-3, 4.1666666666666664354e-2);
    double p67 = fma(r, 1.9841269841269841253e-4, 1.3888888888888889419e-3);
    double p89 = fma(r, 2.7557319223985890653e-6, 2.4801587301587301566e-5);
    double r2 = r * r;
    double q0 = fma(r2, p23, p01);
    double q1 = fma(r2, p67, p45);
    double r4 = r2 * r2;
    double s0 = fma(r4, q1, q0);
    double r8 = r4 * r4;
    double res = fma(r8, p89, s0);
    long long ni = (long long)n;
    double sc = __longlong_as_double((ni + 1023LL) << 52);  // exact 2^n
    return res * sc;
}

// 1/d via fp32 rcp seed + 1 fp64 Newton step (rel err ~2^-44)
__device__ __forceinline__ double fast_recip(double d) {
    double y = (double)__frcp_rn((float)d);
    return y * fma(-d, y, 2.0);
}

// ---------------------------------------------------------------------------
// ONE kernel, grid = 256 x 256. No separate head block.
// Each block (row = bid): MLP term -> atomicAdd-with-return into g_acc
// (count in bits >=55, exact biased fixed-point sum below). The 256th adder
// is the PUBLISHER: it holds the full exact sum in the return value ->
// publishes the fp32 ESTIMATE immediately; the exact fp64 head is computed
// after its window loads are issued and published second.
// POLLING DISCIPLINE (the R14 lesson): ONLY tid0 of each block polls the
// packed epoch words (256 pollers, not 65536) and relays via __syncthreads.
// Deadlock-free: exactly one publisher per replay; every tid0 captures the
// old epoch BEFORE its own add (fence-ordered) and the publish happens only
// after all 256 adds; all polls terminate. No waits form a cycle.
// ---------------------------------------------------------------------------
__global__ void __launch_bounds__(256) fused_attn_kernel(
        const float* __restrict__ hs,
        const float* __restrict__ ht,
        const float* __restrict__ fc1_w,
        const float* __restrict__ fc1_b,
        const float* __restrict__ fc2_w,
        const float* __restrict__ fc2_b,
        float* __restrict__ out, int S) {
    const int tid  = threadIdx.x;
    const int lane = tid & 31;
    const int wid  = tid >> 5;
    const int row  = blockIdx.x;

    __shared__ float    sred[8];
    __shared__ int      sh_est_lo;
    __shared__ int      sh_k;
    __shared__ float    sh_et;

    // early scalar prefetch (lands under the vector load batch)
    float bf = 0.f, fw = 0.f, fb2 = 0.f;
    if (tid == 0) {
        bf  = __ldg(&fc1_b[row]);
        fw  = __ldg(&fc2_w[row]);
        fb2 = __ldg(&fc2_b[0]);
    }

    // ------------------- stage A: MLP row -------------------
    float4 w = ((const float4*)(fc1_w + (size_t)row * HIDDEN))[tid];
    float4 h = ((const float4*)ht)[tid];
    double e0 = fma((double)w.y, (double)h.y, (double)w.x * h.x);
    double e1 = fma((double)w.w, (double)h.w, (double)w.z * h.z);
    float accf = (float)(e0 + e1);
    #pragma unroll
    for (int o = 16; o > 0; o >>= 1)
        accf += __shfl_down_sync(0xffffffffu, accf, o);
    if (lane == 0) sred[wid] = accf;
    __syncthreads();                                   // S1

    bool   is_pub = false;
    double z_pub  = 0.0;
    if (tid == 0) {
        // capture old epoch BEFORE our add (fence-ordered): race-free
        unsigned long long west = *(volatile unsigned long long*)&g_est;
        unsigned old_ep = (unsigned)((west >> 49) & 0x7FFFULL);
        __threadfence();

        float zf = ((sred[0] + sred[1]) + (sred[2] + sred[3]))
                 + ((sred[4] + sred[5]) + (sred[6] + sred[7]))
                 + bf;
        float term = tanhf(zf) * fw;
        long long fx = __float2ll_rn(term * FIX_SCALE);       // exact
        unsigned long long mine = (1ULL << CNT_SHIFT)
                                + (unsigned long long)(fx + FIX_BIAS);
        unsigned long long oldv = atomicAdd(&g_acc, mine);

        unsigned tgt = (old_ep + 1u) & 0x7FFFu;
        if ((oldv >> CNT_SHIFT) == (unsigned long long)(NINTER - 1)) {
            // PUBLISHER: full exact sum in hand -> estimate out immediately
            is_pub = true;
            long long lows = (long long)((oldv + mine) & LOW_MASK);
            long long sum_fx = lows - ((long long)NINTER << FIX_BITS);
            z_pub = (double)sum_fx * (1.0 / (double)(1LL << FIX_BITS))
                  + (double)fb2;
            float zf2 = (float)z_pub;
            float ptf = (float)S * __frcp_rn(1.0f + __expf(-zf2));
            int est_lo = (int)ptf - ((WINDOW - 1) + PAD);
            if (est_lo < 0) est_lo = 0;
            *(volatile unsigned long long*)&g_est =
                ((unsigned long long)tgt << 49)
              | ((unsigned long long)(unsigned)est_lo << 32);
            sh_est_lo = est_lo;
        } else {
            // single poller per block (no L2 spin-storm)
            do {
                west = *(volatile unsigned long long*)&g_est;
            } while ((unsigned)((west >> 49) & 0x7FFFULL) != tgt);
            sh_est_lo = (int)((west >> 32) & 0x1FFFFULL);
        }
    }
    __syncthreads();                                   // S2

    // speculative padded window loads (PAD=8 covers fp32-estimate error)
    const int est_lo = sh_est_lo;
    const int col    = (row << 2) + (tid & 3);
    const int rowoff = tid >> 2;                       // 0..63
    const float* base = hs + col;
    const int r0 = est_lo + rowoff;
    const int r1 = r0 + 64;
    const int r2 = r0 + 128;

    float v0 = 0.f, v1 = 0.f, v2 = 0.f;
    if (r0 < S) v0 = base[(size_t)r0 * HIDDEN];
    if (r1 < S) v1 = base[(size_t)r1 * HIDDEN];
    if (r2 < S) v2 = base[(size_t)r2 * HIDDEN];

    // exact head: publisher computes it under its in-flight loads;
    // everyone else's tid0 polls (lands under their loads too)
    if (tid == 0) {
        unsigned long long west = *(volatile unsigned long long*)&g_est;
        unsigned tgt = (unsigned)((west >> 49) & 0x7FFFULL);
        if (is_pub) {
            double e  = fast_exp(-z_pub);
            double pt = (double)S * fast_recip(1.0 + e);
            int kk = (int)pt;                          // pt in (0,S), non-int
            float et = __expf((float)(((double)S - pt) * (1.0 / 2048.0)));
            *(volatile unsigned long long*)&g_exact =
                ((unsigned long long)tgt << 49)
              | ((unsigned long long)(unsigned)kk << 32)
              | (unsigned long long)(unsigned)__float_as_int(et);
            *(volatile unsigned long long*)&g_acc = 0ULL;   // reset for next replay
            sh_k  = kk;
            sh_et = et;
        } else {
            unsigned long long wex;
            do {
                wex = *(volatile unsigned long long*)&g_exact;
            } while ((unsigned)((wex >> 49) & 0x7FFFULL) != tgt);
            sh_k  = (int)((wex >> 32) & 0x1FFFFULL);
            sh_et = __int_as_float((int)(unsigned)wex);
        }
    }
    __syncthreads();                                   // S3

    const int   k  = sh_k;
    const float et = sh_et;
    int ws = k - (WINDOW - 1);  if (ws < 0)     ws = 0;
    int we = k + WINDOW;        if (we > S - 1) we = S - 1;

    float acc = 0.f;
    if (r0 >= ws && r0 <= we) acc += v0;
    if (r1 >= ws && r1 <= we) acc += v1;
    if (r2 >= ws && r2 <= we) acc += v2;

    // fold the 8 rowgroups within each warp (keeps the 4 column lanes)
    #pragma unroll
    for (int o = 16; o >= 4; o >>= 1)
        acc += __shfl_xor_sync(0xffffffffu, acc, o);

    __shared__ float colsum[8][36];
    if (lane < 4) colsum[wid][lane] = acc;             // 8 warps x 4 cols
    __syncthreads();                                   // S4

    if (tid < 4) {
        float s = ((colsum[0][tid] + colsum[1][tid])
                 + (colsum[2][tid] + colsum[3][tid]))
                + ((colsum[4][tid] + colsum[5][tid])
                 + (colsum[6][tid] + colsum[7][tid]));
        out[col] = et * s;
    }
}

extern "C" void kernel_launch(void* const* d_in, const int* in_sizes, int n_in,
                              void* d_out, int out_size) {
    const float* hs    = (const float*)d_in[0];
    const float* ht    = (const float*)d_in[1];
    const float* fc1_w = (const float*)d_in[2];
    const float* fc1_b = (const float*)d_in[3];
    const float* fc2_w = (const float*)d_in[4];
    const float* fc2_b = (const float*)d_in[5];

    const int S = in_sizes[0] / HIDDEN;   // host-side constant, capture-safe

    fused_attn_kernel<<<NINTER, 256>>>(hs, ht, fc1_w, fc1_b, fc2_w, fc2_b,
                                       (float*)d_out, S);
}